// round 6
// baseline (speedup 1.0000x reference)
#include <cuda_runtime.h>
#include <cstdint>

// Gather: out[i, :] = embedding[index[i], :],  D = 64 floats = 16 float4.
// Multi-pass index-range partitioning: pass p touches only table rows in
// [p*U/P, (p+1)*U/P), a ~55MB working set that stays resident in the 126MB
// L2, so duplicate lookups hit L2 instead of re-reading DRAM.
// 16 threads/row, one float4 each, UNROLL=4 front-batched for MLP.
// index = evict_first (re-scanned each pass), output = __stcs stream.

static constexpr int D = 64;
static constexpr int VEC_PER_ROW = D / 4;  // 16
static constexpr int UNROLL = 4;
static constexpr int PASSES = 4;

__device__ __forceinline__ int ldg_idx(const int* p, uint64_t pol) {
    int v;
    asm("ld.global.nc.L2::cache_hint.b32 %0, [%1], %2;"
        : "=r"(v)
        : "l"(p), "l"(pol));
    return v;
}

__global__ __launch_bounds__(256) void gather_pass_kernel(
    const float4* __restrict__ emb,   // [U, 16] as float4
    const int*    __restrict__ idx,   // [N]
    float4*       __restrict__ out,   // [N, 16] as float4
    int64_t n_vec,                    // N * 16
    int lo, int hi)                   // index range for this pass
{
    uint64_t pol_first;
    asm("createpolicy.fractional.L2::evict_first.b64 %0, 1.0;" : "=l"(pol_first));

    const int64_t stride = (int64_t)gridDim.x * blockDim.x;
    int64_t g = (int64_t)blockIdx.x * blockDim.x + threadIdx.x;

    while (g + (UNROLL - 1) * stride < n_vec) {
        int64_t gg[UNROLL];
        int     src[UNROLL];
        bool    act[UNROLL];
#pragma unroll
        for (int u = 0; u < UNROLL; u++) {
            gg[u] = g + u * stride;
            src[u] = ldg_idx(&idx[gg[u] >> 4], pol_first);
            act[u] = (src[u] >= lo) & (src[u] < hi);
        }
        float4 v[UNROLL];
#pragma unroll
        for (int u = 0; u < UNROLL; u++) {
            if (act[u]) {
                int seg = (int)(gg[u] & 15);
                v[u] = __ldg(&emb[(int64_t)src[u] * VEC_PER_ROW + seg]);
            }
        }
#pragma unroll
        for (int u = 0; u < UNROLL; u++) {
            if (act[u]) __stcs(&out[gg[u]], v[u]);
        }
        g += UNROLL * stride;
    }
    while (g < n_vec) {
        int src = ldg_idx(&idx[g >> 4], pol_first);
        if (src >= lo && src < hi) {
            int seg = (int)(g & 15);
            float4 v = __ldg(&emb[(int64_t)src * VEC_PER_ROW + seg]);
            __stcs(&out[g], v);
        }
        g += stride;
    }
}

extern "C" void kernel_launch(void* const* d_in, const int* in_sizes, int n_in,
                              void* d_out, int out_size) {
    const float4* emb = (const float4*)d_in[0];  // embedding [U, 64] f32
    const int*    idx = (const int*)d_in[1];     // index [N] i32
    float4*       out = (float4*)d_out;

    int64_t n_emb = in_sizes[0];          // U * 64
    int     U     = (int)(n_emb / D);     // 1048576
    int64_t n     = in_sizes[1];          // N = 2097152
    int64_t n_vec = n * VEC_PER_ROW;      // 33,554,432 float4s

    const int threads = 256;
    int64_t blocks = (n_vec + (int64_t)threads * UNROLL - 1) /
                     ((int64_t)threads * UNROLL);   // 32768

    int chunk = (U + PASSES - 1) / PASSES;
    for (int p = 0; p < PASSES; p++) {
        int lo = p * chunk;
        int hi = (p == PASSES - 1) ? U : lo + chunk;
        gather_pass_kernel<<<(unsigned)blocks, threads>>>(
            emb, idx, out, n_vec, lo, hi);
    }
}

// round 7
// speedup vs baseline: 2.2865x; 2.2865x over previous
#include <cuda_runtime.h>
#include <cstdint>

// out[i, :] = embedding[index[i], :],  U=1M rows, D=64 f32 (256B/row), N=2M.
//
// Strategy: partition-then-gather.
//  1) partition_kernel buckets lookup ids into P=4 ranges of the table
//     (64MB slices). Block-aggregated histogram + ballot-ranked scatter of
//     (orig_pos, index) pairs into __device__ scratch.
//  2) 4 sequential dense gather passes; each pass's table slice (~58MB of
//     unique lines) stays L2-resident, so duplicate lookups hit L2 instead
//     of re-reading DRAM. Every lane does real work (unlike predicated
//     multi-pass, which collapsed MLP).
// Output rows are written exactly once -> deterministic regardless of
// scratch ordering. All launches graph-capturable; scratch is static
// __device__ memory (no runtime allocation).

static constexpr int D = 64;
static constexpr int VEC_PER_ROW = D / 4;   // 16
static constexpr int UNROLL = 4;
static constexpr int P = 4;
static constexpr int N_MAX = 1 << 21;       // 2M lookups supported

__device__ int  g_cnt[P];
__device__ int2 g_pairs[P][N_MAX];          // (orig_pos, index_value)

// ---------------------------------------------------------------- reset
__global__ void reset_kernel() {
    if (threadIdx.x < P) g_cnt[threadIdx.x] = 0;
}

// ------------------------------------------------------------- partition
static constexpr int PART_THREADS = 256;
static constexpr int PART_ITEMS_PER_THREAD = 8;
static constexpr int PART_ITEMS = PART_THREADS * PART_ITEMS_PER_THREAD; // 2048

__global__ __launch_bounds__(PART_THREADS) void partition_kernel(
    const int* __restrict__ idx, int n, int shift)
{
    __shared__ int s_cnt[P];
    __shared__ int s_base[P];
    __shared__ int s_cur[P];

    const int tid  = threadIdx.x;
    const int lane = tid & 31;
    if (tid < P) { s_cnt[tid] = 0; s_cur[tid] = 0; }
    __syncthreads();

    const int base_i = blockIdx.x * PART_ITEMS;
    int vals[PART_ITEMS_PER_THREAD];
    int bkt [PART_ITEMS_PER_THREAD];

    // Phase A: load + count (warp-aggregated).
#pragma unroll
    for (int j = 0; j < PART_ITEMS_PER_THREAD; j++) {
        int i = base_i + j * PART_THREADS + tid;
        int v = (i < n) ? __ldg(&idx[i]) : -1;
        vals[j] = v;
        bkt[j]  = (v >= 0) ? (v >> shift) : -1;
#pragma unroll
        for (int k = 0; k < P; k++) {
            unsigned m = __ballot_sync(0xffffffffu, bkt[j] == k);
            if (bkt[j] == k && lane == (__ffs(m) - 1))
                atomicAdd(&s_cnt[k], __popc(m));
        }
    }
    __syncthreads();

    // Phase B: reserve global space (4 atomics per block).
    if (tid < P) s_base[tid] = atomicAdd(&g_cnt[tid], s_cnt[tid]);
    __syncthreads();

    // Phase C: ballot-ranked scatter.
#pragma unroll
    for (int j = 0; j < PART_ITEMS_PER_THREAD; j++) {
        int b = bkt[j];
#pragma unroll
        for (int k = 0; k < P; k++) {
            unsigned m = __ballot_sync(0xffffffffu, b == k);
            if (b == k) {
                int leader = __ffs(m) - 1;
                int prefix = __popc(m & ((1u << lane) - 1u));
                int wbase;
                if (lane == leader) wbase = atomicAdd(&s_cur[k], __popc(m));
                wbase = __shfl_sync(m, wbase, leader);
                int pos = s_base[k] + wbase + prefix;
                g_pairs[k][pos] = make_int2(base_i + j * PART_THREADS + tid,
                                            vals[j]);
            }
        }
    }
}

// ---------------------------------------------------------------- gather
__global__ __launch_bounds__(256) void gather_bucket_kernel(
    const float4* __restrict__ emb,
    float4*       __restrict__ out,
    int pass)
{
    const int   n_p   = g_cnt[pass];
    const int64_t n_vec = (int64_t)n_p * VEC_PER_ROW;
    const int2* __restrict__ pairs = g_pairs[pass];

    const int64_t stride = (int64_t)gridDim.x * blockDim.x;
    int64_t g = (int64_t)blockIdx.x * blockDim.x + threadIdx.x;

    while (g + (UNROLL - 1) * stride < n_vec) {
        int64_t gg[UNROLL];
        int2    pr[UNROLL];
#pragma unroll
        for (int u = 0; u < UNROLL; u++) {
            gg[u] = g + u * stride;
            pr[u] = __ldg(&pairs[gg[u] >> 4]);
        }
        float4 v[UNROLL];
#pragma unroll
        for (int u = 0; u < UNROLL; u++) {
            int seg = (int)(gg[u] & 15);
            v[u] = __ldg(&emb[(int64_t)pr[u].y * VEC_PER_ROW + seg]);
        }
#pragma unroll
        for (int u = 0; u < UNROLL; u++) {
            int seg = (int)(gg[u] & 15);
            __stcs(&out[(int64_t)pr[u].x * VEC_PER_ROW + seg], v[u]);
        }
        g += UNROLL * stride;
    }
    while (g < n_vec) {
        int2 pr = __ldg(&pairs[g >> 4]);
        int seg = (int)(g & 15);
        float4 v = __ldg(&emb[(int64_t)pr.y * VEC_PER_ROW + seg]);
        __stcs(&out[(int64_t)pr.x * VEC_PER_ROW + seg], v);
        g += stride;
    }
}

// -------------------------------------------------- fallback plain gather
__global__ __launch_bounds__(256) void gather_plain_kernel(
    const float4* __restrict__ emb,
    const int*    __restrict__ idx,
    float4*       __restrict__ out,
    int64_t n_vec)
{
    const int64_t stride = (int64_t)gridDim.x * blockDim.x;
    int64_t g = (int64_t)blockIdx.x * blockDim.x + threadIdx.x;
    while (g + (UNROLL - 1) * stride < n_vec) {
        int64_t gg[UNROLL];
        int     src[UNROLL];
#pragma unroll
        for (int u = 0; u < UNROLL; u++) {
            gg[u] = g + u * stride;
            src[u] = __ldg(&idx[gg[u] >> 4]);
        }
        float4 v[UNROLL];
#pragma unroll
        for (int u = 0; u < UNROLL; u++) {
            int seg = (int)(gg[u] & 15);
            v[u] = __ldg(&emb[(int64_t)src[u] * VEC_PER_ROW + seg]);
        }
#pragma unroll
        for (int u = 0; u < UNROLL; u++) __stcs(&out[gg[u]], v[u]);
        g += UNROLL * stride;
    }
    while (g < n_vec) {
        int src = __ldg(&idx[g >> 4]);
        int seg = (int)(g & 15);
        float4 v = __ldg(&emb[(int64_t)src * VEC_PER_ROW + seg]);
        __stcs(&out[g], v);
        g += stride;
    }
}

extern "C" void kernel_launch(void* const* d_in, const int* in_sizes, int n_in,
                              void* d_out, int out_size) {
    const float4* emb = (const float4*)d_in[0];  // embedding [U, 64] f32
    const int*    idx = (const int*)d_in[1];     // index [N] i32
    float4*       out = (float4*)d_out;

    int64_t n_emb = in_sizes[0];
    int     U     = (int)(n_emb / D);            // 1048576
    int64_t n     = in_sizes[1];                 // 2097152
    int64_t n_vec = n * VEC_PER_ROW;

    const int threads = 256;
    bool pow2 = (U > 0) && ((U & (U - 1)) == 0) && (U % P == 0);

    if (!pow2 || n > N_MAX) {
        int64_t blocks = (n_vec + (int64_t)threads * UNROLL - 1) /
                         ((int64_t)threads * UNROLL);
        gather_plain_kernel<<<(unsigned)blocks, threads>>>(emb, idx, out, n_vec);
        return;
    }

    int chunk = U / P;                    // 262144
    int shift = 0;
    while ((1 << shift) < chunk) shift++; // 18

    reset_kernel<<<1, 32>>>();

    int part_blocks = (int)((n + PART_ITEMS - 1) / PART_ITEMS);   // 1024
    partition_kernel<<<part_blocks, PART_THREADS>>>(idx, (int)n, shift);

    // Expected per-pass work ~ n/P rows -> n/P*16 vecs; grid-stride absorbs
    // the binomial variance in bucket sizes.
    int64_t vec_per_pass = (n / P) * VEC_PER_ROW;
    int64_t gblocks = (vec_per_pass + (int64_t)threads * UNROLL - 1) /
                      ((int64_t)threads * UNROLL);                // 8192
    for (int p = 0; p < P; p++) {
        gather_bucket_kernel<<<(unsigned)gblocks, threads>>>(emb, out, p);
    }
}